// round 6
// baseline (speedup 1.0000x reference)
#include <cuda_runtime.h>
#include <cuda_bf16.h>
#include <math.h>

#define N_DB   200000
#define D_EMB  512
#define TOP_K  32

#define NBLK_A 256
#define TPB_A  256
#define ROWS_PER_BLK ((N_DB + NBLK_A - 1) / NBLK_A)   // 782

#define TPB_B  1024
#define N_CAND (NBLK_A * TOP_K)                        // 8192

// Scratch (allocation-free rule: __device__ globals)
__device__ float g_cand_d[N_CAND];
__device__ int   g_cand_i[N_CAND];

// ---------------------------------------------------------------------------
// Stage A: streaming distance computation + per-block top-32 extraction.
// ---------------------------------------------------------------------------
__global__ void __launch_bounds__(TPB_A)
knn_stageA(const float* __restrict__ x, const float* __restrict__ emb)
{
    __shared__ float4 sx4[D_EMB / 4];                 // query, 2KB
    __shared__ float  sd[ROWS_PER_BLK];               // distances^2, ~3.1KB
    __shared__ float  red_d[TPB_A];
    __shared__ int    red_i[TPB_A];

    const int tid  = threadIdx.x;
    const int lane = tid & 31;
    const int wid  = tid >> 5;

    for (int i = tid; i < D_EMB / 4; i += TPB_A)
        sx4[i] = ((const float4*)x)[i];
    __syncthreads();

    const int base = blockIdx.x * ROWS_PER_BLK;
    const int rows = min(ROWS_PER_BLK, N_DB - base);

    for (int r = wid; r < rows; r += TPB_A / 32) {
        const float4* p = (const float4*)(emb + (size_t)(base + r) * D_EMB);
        float acc = 0.f;
        #pragma unroll
        for (int c = 0; c < 4; c++) {
            int j = c * 32 + lane;
            float4 v = p[j];
            float4 q = sx4[j];
            float dx = v.x - q.x, dy = v.y - q.y, dz = v.z - q.z, dw = v.w - q.w;
            acc += dx * dx + dy * dy + dz * dz + dw * dw;
        }
        #pragma unroll
        for (int o = 16; o > 0; o >>= 1)
            acc += __shfl_down_sync(0xffffffffu, acc, o);
        if (lane == 0) sd[r] = acc;
    }
    __syncthreads();

    // 32 extract-min rounds (tie-break: smaller index wins, matches top_k)
    for (int s = 0; s < TOP_K; s++) {
        float bd = INFINITY;
        int   bi = 0x7fffffff;
        for (int j = tid; j < rows; j += TPB_A) {
            float d = sd[j];
            if (d < bd || (d == bd && j < bi)) { bd = d; bi = j; }
        }
        red_d[tid] = bd; red_i[tid] = bi;
        __syncthreads();
        #pragma unroll
        for (int o = TPB_A / 2; o >= 32; o >>= 1) {
            if (tid < o) {
                float od = red_d[tid + o]; int oi = red_i[tid + o];
                if (od < red_d[tid] || (od == red_d[tid] && oi < red_i[tid])) {
                    red_d[tid] = od; red_i[tid] = oi;
                }
            }
            __syncthreads();
        }
        if (tid < 32) {
            float bd2 = red_d[tid]; int bi2 = red_i[tid];
            #pragma unroll
            for (int o = 16; o > 0; o >>= 1) {
                float od = __shfl_down_sync(0xffffffffu, bd2, o);
                int   oi = __shfl_down_sync(0xffffffffu, bi2, o);
                if (od < bd2 || (od == bd2 && oi < bi2)) { bd2 = od; bi2 = oi; }
            }
            if (tid == 0) {
                g_cand_d[blockIdx.x * TOP_K + s] = bd2;
                g_cand_i[blockIdx.x * TOP_K + s] = base + bi2;
                sd[bi2] = INFINITY;
            }
        }
        __syncthreads();
    }
}

// ---------------------------------------------------------------------------
// Stage B: merge 8192 candidates -> global top-32 (sorted ascending),
// gather embeddings/classes, write output (ALL float32, elementwise packed):
//   elems [0, 16384)      : nbr_emb  (32 x 512), row-major
//   elems [16384, 16416)  : nbr_cls  (int32 classes cast to float)
//   elems [16416, 16448)  : nbr_dist (ascending)
// ---------------------------------------------------------------------------
__global__ void __launch_bounds__(TPB_B)
knn_stageB(const float* __restrict__ emb, const int* __restrict__ cls,
           float* __restrict__ out)
{
    __shared__ float red_d[TPB_B];
    __shared__ int   red_r[TPB_B];
    __shared__ int   red_p[TPB_B];
    __shared__ int   sel_i[TOP_K];
    __shared__ float sel_d[TOP_K];

    const int tid = threadIdx.x;

    for (int s = 0; s < TOP_K; s++) {
        float bd = INFINITY;
        int   br = 0x7fffffff;
        int   bp = -1;
        #pragma unroll
        for (int j = tid; j < N_CAND; j += TPB_B) {
            float d = g_cand_d[j];
            int   r = g_cand_i[j];
            if (d < bd || (d == bd && r < br)) { bd = d; br = r; bp = j; }
        }
        red_d[tid] = bd; red_r[tid] = br; red_p[tid] = bp;
        __syncthreads();
        #pragma unroll
        for (int o = TPB_B / 2; o >= 32; o >>= 1) {
            if (tid < o) {
                float od = red_d[tid + o]; int orr = red_r[tid + o];
                if (od < red_d[tid] || (od == red_d[tid] && orr < red_r[tid])) {
                    red_d[tid] = od; red_r[tid] = orr; red_p[tid] = red_p[tid + o];
                }
            }
            __syncthreads();
        }
        if (tid < 32) {
            float bd2 = red_d[tid]; int br2 = red_r[tid]; int bp2 = red_p[tid];
            #pragma unroll
            for (int o = 16; o > 0; o >>= 1) {
                float od = __shfl_down_sync(0xffffffffu, bd2, o);
                int   orr = __shfl_down_sync(0xffffffffu, br2, o);
                int   op = __shfl_down_sync(0xffffffffu, bp2, o);
                if (od < bd2 || (od == bd2 && orr < br2)) { bd2 = od; br2 = orr; bp2 = op; }
            }
            if (tid == 0) {
                sel_d[s] = bd2;
                sel_i[s] = br2;
                g_cand_d[bp2] = INFINITY;
            }
        }
        __syncthreads();
    }

    // gather neighbor embeddings (32 x 512 floats, coalesced per row)
    for (int i = tid; i < TOP_K * D_EMB; i += TPB_B) {
        int r = i >> 9;
        int c = i & 511;
        out[i] = emb[(size_t)sel_i[r] * D_EMB + c];
    }

    // classes (int32 input) cast to float; dists (sqrt) after them
    if (tid < TOP_K) {
        out[TOP_K * D_EMB + tid]         = (float)cls[sel_i[tid]];
        out[TOP_K * D_EMB + TOP_K + tid] = sqrtf(sel_d[tid]);
    }
}

extern "C" void kernel_launch(void* const* d_in, const int* in_sizes, int n_in,
                              void* d_out, int out_size)
{
    const float* x   = (const float*)d_in[0];      // [1, 512] f32
    const float* emb = (const float*)d_in[1];      // [200000, 512] f32
    const int*   cls = (const int*)d_in[2];        // [200000] int32 (JAX x64 off)
    // d_in[3] is k (scalar), fixed at 32
    float* out = (float*)d_out;

    knn_stageA<<<NBLK_A, TPB_A>>>(x, emb);
    knn_stageB<<<1, TPB_B>>>(emb, cls, out);
}

// round 7
// speedup vs baseline: 1.1548x; 1.1548x over previous
#include <cuda_runtime.h>
#include <cuda_bf16.h>
#include <math.h>

#define N_DB   200000
#define D_EMB  512
#define TOP_K  32

#define TPB_A  256
#define NBLK_A 740                       // ~5 CTAs/SM on 148 SMs
#define WARPS_A (NBLK_A * (TPB_A / 32)) // 5920 warps

#define TPB_B  1024
#define ELEMS_PER_THR ((N_DB + TPB_B - 1) / TPB_B)   // 196

#define IDX_INF 0x7fffffff

// Scratch (allocation-free rule: __device__ global)
__device__ float g_dist[N_DB];

// ---------------------------------------------------------------------------
// Stage A: pure streaming. One warp per row; each lane reads 4 float4 chunks
// (coalesced 2KB row), squared-diff accumulate, shuffle-reduce, lane0 stores
// the squared distance. No shared memory, no barriers, nothing but bandwidth.
// ---------------------------------------------------------------------------
__global__ void __launch_bounds__(TPB_A)
knn_dist(const float* __restrict__ x, const float* __restrict__ emb)
{
    const int lane = threadIdx.x & 31;
    const int gw   = blockIdx.x * (TPB_A / 32) + (threadIdx.x >> 5);

    // query chunks for this lane, held in registers for the whole kernel
    const float4* x4 = (const float4*)x;
    const float4 q0 = x4[lane];
    const float4 q1 = x4[32 + lane];
    const float4 q2 = x4[64 + lane];
    const float4 q3 = x4[96 + lane];

    for (int r = gw; r < N_DB; r += WARPS_A) {
        const float4* p = (const float4*)(emb + (size_t)r * D_EMB);
        float4 v0 = p[lane];
        float4 v1 = p[32 + lane];
        float4 v2 = p[64 + lane];
        float4 v3 = p[96 + lane];

        float acc;
        float d;
        d = v0.x - q0.x; acc  = d * d;
        d = v0.y - q0.y; acc += d * d;
        d = v0.z - q0.z; acc += d * d;
        d = v0.w - q0.w; acc += d * d;
        d = v1.x - q1.x; acc += d * d;
        d = v1.y - q1.y; acc += d * d;
        d = v1.z - q1.z; acc += d * d;
        d = v1.w - q1.w; acc += d * d;
        d = v2.x - q2.x; acc += d * d;
        d = v2.y - q2.y; acc += d * d;
        d = v2.z - q2.z; acc += d * d;
        d = v2.w - q2.w; acc += d * d;
        d = v3.x - q3.x; acc += d * d;
        d = v3.y - q3.y; acc += d * d;
        d = v3.z - q3.z; acc += d * d;
        d = v3.w - q3.w; acc += d * d;

        #pragma unroll
        for (int o = 16; o > 0; o >>= 1)
            acc += __shfl_down_sync(0xffffffffu, acc, o);
        if (lane == 0) g_dist[r] = acc;
    }
}

// ---------------------------------------------------------------------------
// Stage B: single block, top-2-per-thread cached 32-round extract-min, then
// gather. Thread t owns g_dist[t + 1024*i]. On winning, the owner marks its
// slot INF, promotes its cached second-best, and only rescans its slice if
// both cached entries were consumed (rare).
// Output (all float32):
//   [0, 16384)     nbr_emb (32 x 512)
//   [16384, 16416) nbr_cls (int32 cast to float)
//   [16416, 16448) nbr_dist (ascending)
// ---------------------------------------------------------------------------
__global__ void __launch_bounds__(TPB_B)
knn_select(const float* __restrict__ emb, const int* __restrict__ cls,
           float* __restrict__ out)
{
    __shared__ float wd[32];
    __shared__ int   wi[32];
    __shared__ int   s_win;
    __shared__ int   sel_i[TOP_K];
    __shared__ float sel_d[TOP_K];

    const int tid  = threadIdx.x;
    const int lane = tid & 31;
    const int wid  = tid >> 5;

    // initial scan: per-thread best & second-best over its strided slice
    float b1 = INFINITY, b2 = INFINITY;
    int   i1 = IDX_INF,  i2 = IDX_INF;
    for (int j = tid; j < N_DB; j += TPB_B) {
        float v = g_dist[j];
        if (v < b1 || (v == b1 && j < i1)) {
            b2 = b1; i2 = i1; b1 = v; i1 = j;
        } else if (v < b2 || (v == b2 && j < i2)) {
            b2 = v; i2 = j;
        }
    }

    for (int s = 0; s < TOP_K; s++) {
        // warp argmin of thread bests
        float d = b1; int i = i1;
        #pragma unroll
        for (int o = 16; o > 0; o >>= 1) {
            float od = __shfl_down_sync(0xffffffffu, d, o);
            int   oi = __shfl_down_sync(0xffffffffu, i, o);
            if (od < d || (od == d && oi < i)) { d = od; i = oi; }
        }
        if (lane == 0) { wd[wid] = d; wi[wid] = i; }
        __syncthreads();
        if (tid < 32) {
            d = wd[tid]; i = wi[tid];
            #pragma unroll
            for (int o = 16; o > 0; o >>= 1) {
                float od = __shfl_down_sync(0xffffffffu, d, o);
                int   oi = __shfl_down_sync(0xffffffffu, i, o);
                if (od < d || (od == d && oi < i)) { d = od; i = oi; }
            }
            if (tid == 0) { s_win = i; sel_i[s] = i; sel_d[s] = d; }
        }
        __syncthreads();

        const int w = s_win;
        if ((w & (TPB_B - 1)) == tid) {      // owner thread (w mod 1024 == tid)
            g_dist[w] = INFINITY;            // own slice: no cross-thread race
            if (w == i1) {
                b1 = b2; i1 = i2;
                b2 = INFINITY; i2 = IDX_INF;
                if (i1 == IDX_INF) {
                    // both cached entries consumed: rescan slice (rare)
                    for (int j = tid; j < N_DB; j += TPB_B) {
                        float v = g_dist[j];
                        if (v < b1 || (v == b1 && j < i1)) {
                            b2 = b1; i2 = i1; b1 = v; i1 = j;
                        } else if (v < b2 || (v == b2 && j < i2)) {
                            b2 = v; i2 = j;
                        }
                    }
                }
            }
        }
        __syncthreads();
    }

    // gather neighbor embeddings (32 x 512 floats, coalesced per row)
    for (int i = tid; i < TOP_K * D_EMB; i += TPB_B) {
        int r = i >> 9;
        int c = i & 511;
        out[i] = emb[(size_t)sel_i[r] * D_EMB + c];
    }

    // classes (int32 input) cast to float; dists (sqrt) after them
    if (tid < TOP_K) {
        out[TOP_K * D_EMB + tid]         = (float)cls[sel_i[tid]];
        out[TOP_K * D_EMB + TOP_K + tid] = sqrtf(sel_d[tid]);
    }
}

extern "C" void kernel_launch(void* const* d_in, const int* in_sizes, int n_in,
                              void* d_out, int out_size)
{
    const float* x   = (const float*)d_in[0];      // [1, 512] f32
    const float* emb = (const float*)d_in[1];      // [200000, 512] f32
    const int*   cls = (const int*)d_in[2];        // [200000] int32
    // d_in[3] is k (scalar), fixed at 32
    float* out = (float*)d_out;

    knn_dist<<<NBLK_A, TPB_A>>>(x, emb);
    knn_select<<<1, TPB_B>>>(emb, cls, out);
}

// round 8
// speedup vs baseline: 1.6494x; 1.4283x over previous
#include <cuda_runtime.h>
#include <cuda_bf16.h>
#include <math.h>

#define N_DB   200000
#define D_EMB  512
#define TOP_K  32

// ---- Stage A: streaming distances (at HBM roofline, do not touch) ----
#define TPB_A  256
#define NBLK_A 740
#define WARPS_A (NBLK_A * (TPB_A / 32))

// ---- Stage B1: per-block selection ----
#define NBLK_S 148
#define TPB_S  256
#define ROWS_S ((N_DB + NBLK_S - 1) / NBLK_S)    // 1352

// ---- Stage B2: final merge ----
#define N_CAND (NBLK_S * TOP_K)                   // 4736
#define TPB_F  1024

#define IDX_INF 0x7fffffff

// Scratch (allocation-free rule: __device__ globals)
__device__ float g_dist[N_DB];
__device__ float g_cand_d[N_CAND];
__device__ int   g_cand_i[N_CAND];

// ---------------------------------------------------------------------------
// Stage A: pure streaming. One warp per row; 16 floats per lane in float4s,
// shuffle-reduce, lane0 stores squared distance. Measured ~7.8 TB/s.
// ---------------------------------------------------------------------------
__global__ void __launch_bounds__(TPB_A)
knn_dist(const float* __restrict__ x, const float* __restrict__ emb)
{
    const int lane = threadIdx.x & 31;
    const int gw   = blockIdx.x * (TPB_A / 32) + (threadIdx.x >> 5);

    const float4* x4 = (const float4*)x;
    const float4 q0 = x4[lane];
    const float4 q1 = x4[32 + lane];
    const float4 q2 = x4[64 + lane];
    const float4 q3 = x4[96 + lane];

    for (int r = gw; r < N_DB; r += WARPS_A) {
        const float4* p = (const float4*)(emb + (size_t)r * D_EMB);
        float4 v0 = p[lane];
        float4 v1 = p[32 + lane];
        float4 v2 = p[64 + lane];
        float4 v3 = p[96 + lane];

        float acc, d;
        d = v0.x - q0.x; acc  = d * d;
        d = v0.y - q0.y; acc += d * d;
        d = v0.z - q0.z; acc += d * d;
        d = v0.w - q0.w; acc += d * d;
        d = v1.x - q1.x; acc += d * d;
        d = v1.y - q1.y; acc += d * d;
        d = v1.z - q1.z; acc += d * d;
        d = v1.w - q1.w; acc += d * d;
        d = v2.x - q2.x; acc += d * d;
        d = v2.y - q2.y; acc += d * d;
        d = v2.z - q2.z; acc += d * d;
        d = v2.w - q2.w; acc += d * d;
        d = v3.x - q3.x; acc += d * d;
        d = v3.y - q3.y; acc += d * d;
        d = v3.z - q3.z; acc += d * d;
        d = v3.w - q3.w; acc += d * d;

        #pragma unroll
        for (int o = 16; o > 0; o >>= 1)
            acc += __shfl_down_sync(0xffffffffu, acc, o);
        if (lane == 0) g_dist[r] = acc;
    }
}

// ---------------------------------------------------------------------------
// Stage B1: each of 148 blocks owns a contiguous ~1352-row slice. Copy the
// slice's distances to smem, run 32 extract-min rounds (tie-break on index),
// emit top-32 (dist, global row) to the candidate buffer.
// ---------------------------------------------------------------------------
__global__ void __launch_bounds__(TPB_S)
knn_block_select()
{
    __shared__ float sd[ROWS_S];
    __shared__ float wd[8];
    __shared__ int   wi[8];

    const int tid  = threadIdx.x;
    const int lane = tid & 31;
    const int wid  = tid >> 5;

    const int base = blockIdx.x * ROWS_S;
    const int rows = min(ROWS_S, N_DB - base);

    for (int j = tid; j < rows; j += TPB_S)
        sd[j] = g_dist[base + j];
    __syncthreads();

    for (int s = 0; s < TOP_K; s++) {
        float bd = INFINITY;
        int   bi = IDX_INF;
        for (int j = tid; j < rows; j += TPB_S) {
            float v = sd[j];
            if (v < bd || (v == bd && j < bi)) { bd = v; bi = j; }
        }
        #pragma unroll
        for (int o = 16; o > 0; o >>= 1) {
            float od = __shfl_down_sync(0xffffffffu, bd, o);
            int   oi = __shfl_down_sync(0xffffffffu, bi, o);
            if (od < bd || (od == bd && oi < bi)) { bd = od; bi = oi; }
        }
        if (lane == 0) { wd[wid] = bd; wi[wid] = bi; }
        __syncthreads();
        if (tid < 32) {
            bd = (tid < 8) ? wd[tid] : INFINITY;
            bi = (tid < 8) ? wi[tid] : IDX_INF;
            #pragma unroll
            for (int o = 4; o > 0; o >>= 1) {
                float od = __shfl_down_sync(0xffffffffu, bd, o);
                int   oi = __shfl_down_sync(0xffffffffu, bi, o);
                if (od < bd || (od == bd && oi < bi)) { bd = od; bi = oi; }
            }
            if (tid == 0) {
                g_cand_d[blockIdx.x * TOP_K + s] = bd;
                g_cand_i[blockIdx.x * TOP_K + s] = base + bi;
                sd[bi] = INFINITY;
            }
        }
        __syncthreads();
    }
}

// ---------------------------------------------------------------------------
// Stage B2: single block merges 4736 candidates -> global top-32 (ascending,
// tie-break on global row index), gathers embeddings, packs output:
//   elems [0, 16384)      nbr_emb (32 x 512)
//   elems [16384, 16416)  nbr_cls (int32 cast to float)
//   elems [16416, 16448)  nbr_dist
// ---------------------------------------------------------------------------
__global__ void __launch_bounds__(TPB_F)
knn_final(const float* __restrict__ emb, const int* __restrict__ cls,
          float* __restrict__ out)
{
    __shared__ float cd[N_CAND];
    __shared__ int   ci[N_CAND];
    __shared__ float wd[32];
    __shared__ int   wi[32];
    __shared__ int   wp[32];
    __shared__ int   sel_i[TOP_K];
    __shared__ float sel_d[TOP_K];

    const int tid  = threadIdx.x;
    const int lane = tid & 31;
    const int wid  = tid >> 5;

    for (int j = tid; j < N_CAND; j += TPB_F) {
        cd[j] = g_cand_d[j];
        ci[j] = g_cand_i[j];
    }
    __syncthreads();

    for (int s = 0; s < TOP_K; s++) {
        float bd = INFINITY;
        int   br = IDX_INF;   // global row index (tie-break key)
        int   bp = -1;        // slot (for marking)
        #pragma unroll
        for (int j = tid; j < N_CAND; j += TPB_F) {
            float v = cd[j];
            int   r = ci[j];
            if (v < bd || (v == bd && r < br)) { bd = v; br = r; bp = j; }
        }
        #pragma unroll
        for (int o = 16; o > 0; o >>= 1) {
            float od = __shfl_down_sync(0xffffffffu, bd, o);
            int   orr = __shfl_down_sync(0xffffffffu, br, o);
            int   op = __shfl_down_sync(0xffffffffu, bp, o);
            if (od < bd || (od == bd && orr < br)) { bd = od; br = orr; bp = op; }
        }
        if (lane == 0) { wd[wid] = bd; wi[wid] = br; wp[wid] = bp; }
        __syncthreads();
        if (tid < 32) {
            bd = wd[tid]; br = wi[tid]; bp = wp[tid];
            #pragma unroll
            for (int o = 16; o > 0; o >>= 1) {
                float od = __shfl_down_sync(0xffffffffu, bd, o);
                int   orr = __shfl_down_sync(0xffffffffu, br, o);
                int   op = __shfl_down_sync(0xffffffffu, bp, o);
                if (od < bd || (od == bd && orr < br)) { bd = od; br = orr; bp = op; }
            }
            if (tid == 0) {
                sel_d[s] = bd;
                sel_i[s] = br;
                cd[bp]   = INFINITY;
            }
        }
        __syncthreads();
    }

    // gather neighbor embeddings (32 x 512 floats, coalesced per row)
    for (int i = tid; i < TOP_K * D_EMB; i += TPB_F) {
        int r = i >> 9;
        int c = i & 511;
        out[i] = emb[(size_t)sel_i[r] * D_EMB + c];
    }

    if (tid < TOP_K) {
        out[TOP_K * D_EMB + tid]         = (float)cls[sel_i[tid]];
        out[TOP_K * D_EMB + TOP_K + tid] = sqrtf(sel_d[tid]);
    }
}

extern "C" void kernel_launch(void* const* d_in, const int* in_sizes, int n_in,
                              void* d_out, int out_size)
{
    const float* x   = (const float*)d_in[0];      // [1, 512] f32
    const float* emb = (const float*)d_in[1];      // [200000, 512] f32
    const int*   cls = (const int*)d_in[2];        // [200000] int32
    // d_in[3] is k (scalar), fixed at 32
    float* out = (float*)d_out;

    knn_dist<<<NBLK_A, TPB_A>>>(x, emb);
    knn_block_select<<<NBLK_S, TPB_S>>>();
    knn_final<<<1, TPB_F>>>(emb, cls, out);
}

// round 9
// speedup vs baseline: 1.8081x; 1.0962x over previous
#include <cuda_runtime.h>
#include <cuda_bf16.h>
#include <math.h>

#define N_DB   200000
#define D_EMB  512
#define TOP_K  32

// ---- Stage A: streaming distances + histogram ----
#define TPB_A  256
#define NBLK_A 740
#define WARPS_A (NBLK_A * (TPB_A / 32))

// histogram: key = float_bits >> 18  (monotone for d >= 0), 8192 bins
#define HSHIFT 18
#define NBINS  8192

// ---- Stage C: threshold + compaction ----
#define TPB_C  1024
#define NBLK_C 148
#define ROWS_C ((N_DB + NBLK_C - 1) / NBLK_C)    // 1352
#define BPT    (NBINS / TPB_C)                   // 8 bins per thread

// ---- Stage D: final select ----
#define TPB_D  1024
#define CAP    4096

#define IDX_INF 0x7fffffff

// Scratch (allocation-free rule: __device__ globals; zero-initialized at load)
__device__ float g_dist[N_DB];
__device__ int   g_hist[NBINS];
__device__ int   g_cnt;
__device__ float g_cd[CAP];
__device__ int   g_ci[CAP];

// ---------------------------------------------------------------------------
// Stage A: pure streaming (measured 6.5 TB/s) + per-block smem histogram.
// One warp per row; lane0 stores dist^2 and bumps its histogram bin.
// ---------------------------------------------------------------------------
__global__ void __launch_bounds__(TPB_A)
knn_dist(const float* __restrict__ x, const float* __restrict__ emb)
{
    __shared__ int sh[NBINS];                    // 32 KB

    const int tid  = threadIdx.x;
    const int lane = tid & 31;
    const int gw   = blockIdx.x * (TPB_A / 32) + (tid >> 5);

    for (int i = tid; i < NBINS; i += TPB_A) sh[i] = 0;

    const float4* x4 = (const float4*)x;
    const float4 q0 = x4[lane];
    const float4 q1 = x4[32 + lane];
    const float4 q2 = x4[64 + lane];
    const float4 q3 = x4[96 + lane];
    __syncthreads();

    for (int r = gw; r < N_DB; r += WARPS_A) {
        const float4* p = (const float4*)(emb + (size_t)r * D_EMB);
        float4 v0 = p[lane];
        float4 v1 = p[32 + lane];
        float4 v2 = p[64 + lane];
        float4 v3 = p[96 + lane];

        float acc, d;
        d = v0.x - q0.x; acc  = d * d;
        d = v0.y - q0.y; acc += d * d;
        d = v0.z - q0.z; acc += d * d;
        d = v0.w - q0.w; acc += d * d;
        d = v1.x - q1.x; acc += d * d;
        d = v1.y - q1.y; acc += d * d;
        d = v1.z - q1.z; acc += d * d;
        d = v1.w - q1.w; acc += d * d;
        d = v2.x - q2.x; acc += d * d;
        d = v2.y - q2.y; acc += d * d;
        d = v2.z - q2.z; acc += d * d;
        d = v2.w - q2.w; acc += d * d;
        d = v3.x - q3.x; acc += d * d;
        d = v3.y - q3.y; acc += d * d;
        d = v3.z - q3.z; acc += d * d;
        d = v3.w - q3.w; acc += d * d;

        #pragma unroll
        for (int o = 16; o > 0; o >>= 1)
            acc += __shfl_down_sync(0xffffffffu, acc, o);
        if (lane == 0) {
            g_dist[r] = acc;
            atomicAdd(&sh[__float_as_uint(acc) >> HSHIFT], 1);
        }
    }
    __syncthreads();

    // merge nonzero bins into global histogram
    for (int i = tid; i < NBINS; i += TPB_A) {
        int v = sh[i];
        if (v) atomicAdd(&g_hist[i], v);
    }
}

// ---------------------------------------------------------------------------
// Stage C: every block finds the 32-crossing histogram bin b* (parallel
// prefix scan over 8192 bins), then compacts its contiguous slice of g_dist:
// elements with key <= b* are written to the candidate buffer.
// ---------------------------------------------------------------------------
__global__ void __launch_bounds__(TPB_C)
knn_compact()
{
    __shared__ int sp[TPB_C];
    __shared__ int s_bstar;

    const int tid = threadIdx.x;

    // per-thread sum of its 8 bins
    int bins[BPT];
    int s = 0;
    const int b0 = tid * BPT;
    #pragma unroll
    for (int i = 0; i < BPT; i++) { bins[i] = g_hist[b0 + i]; s += bins[i]; }

    // Hillis-Steele inclusive scan over 1024 thread sums
    sp[tid] = s;
    __syncthreads();
    int v = s;
    for (int o = 1; o < TPB_C; o <<= 1) {
        int add = (tid >= o) ? sp[tid - o] : 0;
        __syncthreads();
        v += add;
        sp[tid] = v;
        __syncthreads();
    }
    const int excl = v - s;

    // unique thread whose bin range contains the 32nd element
    if (excl < TOP_K && v >= TOP_K) {
        int cum = excl;
        #pragma unroll
        for (int i = 0; i < BPT; i++) {
            cum += bins[i];
            if (cum >= TOP_K) { s_bstar = b0 + i; break; }
        }
    }
    __syncthreads();
    const unsigned kmax = (unsigned)s_bstar;

    // compact this block's contiguous slice
    const int base = blockIdx.x * ROWS_C;
    const int rows = min(ROWS_C, N_DB - base);
    for (int j = tid; j < rows; j += TPB_C) {
        float d = g_dist[base + j];
        if ((__float_as_uint(d) >> HSHIFT) <= kmax) {
            int p = atomicAdd(&g_cnt, 1);
            if (p < CAP) { g_cd[p] = d; g_ci[p] = base + j; }
        }
    }
}

// ---------------------------------------------------------------------------
// Stage D: exact top-32 over the tiny candidate set (tie-break: smaller
// global row index, matching jax.lax.top_k stability), gather + pack output
// (all float32):
//   [0, 16384)     nbr_emb (32 x 512)
//   [16384, 16416) nbr_cls (int32 cast to float)
//   [16416, 16448) nbr_dist (ascending)
// Also re-zeroes histogram + counter so each graph replay starts clean.
// ---------------------------------------------------------------------------
__global__ void __launch_bounds__(TPB_D)
knn_final(const float* __restrict__ emb, const int* __restrict__ cls,
          float* __restrict__ out)
{
    __shared__ float cd[CAP];
    __shared__ int   ci[CAP];
    __shared__ float wd[32];
    __shared__ int   wi[32];
    __shared__ int   wp[32];
    __shared__ int   sel_i[TOP_K];
    __shared__ float sel_d[TOP_K];

    const int tid  = threadIdx.x;
    const int lane = tid & 31;
    const int wid  = tid >> 5;

    const int n = min(g_cnt, CAP);
    for (int j = tid; j < n; j += TPB_D) {
        cd[j] = g_cd[j];
        ci[j] = g_ci[j];
    }
    __syncthreads();

    // cleanup for next replay (after counter read + candidate copy)
    if (tid == 0) g_cnt = 0;
    for (int i = tid; i < NBINS; i += TPB_D) g_hist[i] = 0;

    for (int s = 0; s < TOP_K; s++) {
        float bd = INFINITY;
        int   br = IDX_INF;
        int   bp = -1;
        for (int j = tid; j < n; j += TPB_D) {
            float dv = cd[j];
            int   r  = ci[j];
            if (dv < bd || (dv == bd && r < br)) { bd = dv; br = r; bp = j; }
        }
        #pragma unroll
        for (int o = 16; o > 0; o >>= 1) {
            float od  = __shfl_down_sync(0xffffffffu, bd, o);
            int   orr = __shfl_down_sync(0xffffffffu, br, o);
            int   op  = __shfl_down_sync(0xffffffffu, bp, o);
            if (od < bd || (od == bd && orr < br)) { bd = od; br = orr; bp = op; }
        }
        if (lane == 0) { wd[wid] = bd; wi[wid] = br; wp[wid] = bp; }
        __syncthreads();
        if (tid < 32) {
            bd = wd[tid]; br = wi[tid]; bp = wp[tid];
            #pragma unroll
            for (int o = 16; o > 0; o >>= 1) {
                float od  = __shfl_down_sync(0xffffffffu, bd, o);
                int   orr = __shfl_down_sync(0xffffffffu, br, o);
                int   op  = __shfl_down_sync(0xffffffffu, bp, o);
                if (od < bd || (od == bd && orr < br)) { bd = od; br = orr; bp = op; }
            }
            if (tid == 0) {
                sel_d[s] = bd;
                sel_i[s] = br;
                cd[bp]   = INFINITY;
            }
        }
        __syncthreads();
    }

    // gather neighbor embeddings (32 x 512 floats, coalesced per row)
    for (int i = tid; i < TOP_K * D_EMB; i += TPB_D) {
        int r = i >> 9;
        int c = i & 511;
        out[i] = emb[(size_t)sel_i[r] * D_EMB + c];
    }

    if (tid < TOP_K) {
        out[TOP_K * D_EMB + tid]         = (float)cls[sel_i[tid]];
        out[TOP_K * D_EMB + TOP_K + tid] = sqrtf(sel_d[tid]);
    }
}

extern "C" void kernel_launch(void* const* d_in, const int* in_sizes, int n_in,
                              void* d_out, int out_size)
{
    const float* x   = (const float*)d_in[0];      // [1, 512] f32
    const float* emb = (const float*)d_in[1];      // [200000, 512] f32
    const int*   cls = (const int*)d_in[2];        // [200000] int32
    // d_in[3] is k (scalar), fixed at 32
    float* out = (float*)d_out;

    knn_dist<<<NBLK_A, TPB_A>>>(x, emb);
    knn_compact<<<NBLK_C, TPB_C>>>();
    knn_final<<<1, TPB_D>>>(emb, cls, out);
}